// round 1
// baseline (speedup 1.0000x reference)
#include <cuda_runtime.h>
#include <cstdint>
#include <cstddef>

// ---------------------------------------------------------------------------
// 2-layer LSTM (T=512, B=4096, D=64, H=70) + MLP head, fp32 with packed
// f32x2 FMAs. Two persistent passes (one per LSTM layer) keep each layer's
// weights resident in SMEM; h0 sequence staged in a __device__ global.
// ---------------------------------------------------------------------------

#define TT   512
#define BB   4096
#define DD   64
#define HH   70
#define GG   280          // 4*H
#define BC   32           // batch rows per block
#define NBLK (BB / BC)    // 128 blocks
#define NTHR 256
#define ROWP 288          // padded gate row (8 warps * 36 virtual cols)
#define CPW  35           // real cols per warp
#define VPW  36           // virtual cols per warp (1 garbage)

// scratch: h0 sequence [T][H][B], final h1 [H][B]
__device__ float g_h0[(size_t)TT * HH * BB];
__device__ float g_h1[HH * BB];

#define FMA2(d, a, b) \
    asm("fma.rn.f32x2 %0, %1, %2, %0;" : "+l"(d) : "l"(a), "l"(b))

__device__ __forceinline__ float sigmoidf_(float x) {
    return __fdividef(1.f, 1.f + __expf(-x));
}
__device__ __forceinline__ float tanhf_(float x) {
    return __fdividef(2.f, 1.f + __expf(-2.f * x)) - 1.f;
}

template <int KA, bool IN_TBK, bool WRITE_SEQ, bool FINAL_OUT>
__global__ void __launch_bounds__(NTHR, 1)
lstm_layer(const float* __restrict__ in_seq,
           const float* __restrict__ Wih, const float* __restrict__ Whh,
           const float* __restrict__ bih, const float* __restrict__ bhh,
           float* __restrict__ seq_out, float* __restrict__ fin_out)
{
    extern __shared__ float sm[];
    float* Wa   = sm;                    // [KA][ROWP]  (transposed, warp-padded)
    float* Wb   = Wa + KA * ROWP;        // [HH][ROWP]
    float* bias = Wb + HH * ROWP;        // [ROWP]
    float* inb  = bias + ROWP;           // [KA][33]
    float* hb   = inb + KA * 33;         // [HH][33]
    float* cb   = hb + HH * 33;          // [HH][33]
    float* gb   = cb + HH * 33;          // [GG][33]

    const int tid  = threadIdx.x;
    const int lane = tid & 31;
    const int w    = tid >> 5;
    const int row0 = blockIdx.x * BC;

    // zero weight region (pad cols), bias, and state
    for (int i = tid; i < (KA + HH) * ROWP + ROWP; i += NTHR) sm[i] = 0.f;
    for (int i = tid; i < HH * 33 * 2; i += NTHR) hb[i] = 0.f;
    __syncthreads();

    // load + transpose weights into warp-padded [k][wc*36+i] layout
    for (int idx = tid; idx < GG * KA; idx += NTHR) {
        int j = idx / KA, k = idx - j * KA;
        int wc = j / CPW, i = j - wc * CPW;
        Wa[k * ROWP + wc * VPW + i] = Wih[idx];
    }
    for (int idx = tid; idx < GG * HH; idx += NTHR) {
        int j = idx / HH, k = idx - j * HH;
        int wc = j / CPW, i = j - wc * CPW;
        Wb[k * ROWP + wc * VPW + i] = Whh[idx];
    }
    for (int j = tid; j < GG; j += NTHR) {
        int wc = j / CPW, i = j - wc * CPW;
        bias[wc * VPW + i] = bih[j] + bhh[j];
    }
    __syncthreads();

    const ulonglong2* bias2 =
        reinterpret_cast<const ulonglong2*>(bias + w * VPW);

    for (int t = 0; t < TT; t++) {
        // ---- stage input tile into [k][33] (conflict-free both directions)
        if (!IN_TBK) {
            // in_seq layout [T][B][KA]
            for (int idx = tid; idx < BC * KA; idx += NTHR) {
                int r = idx / KA, k = idx - r * KA;
                inb[k * 33 + r] =
                    in_seq[((size_t)t * BB + row0 + r) * KA + k];
            }
        } else {
            // in_seq layout [T][KA][B]
            for (int idx = tid; idx < BC * KA; idx += NTHR) {
                int k = idx >> 5, r = idx & 31;
                inb[k * 33 + r] =
                    in_seq[((size_t)t * KA + k) * BB + row0 + r];
            }
        }
        __syncthreads();

        // ---- gates GEMM: each warp computes 36 virtual cols x 32 rows
        unsigned long long acc[18];
#pragma unroll
        for (int q = 0; q < 9; q++) {
            ulonglong2 b2 = bias2[q];
            acc[2 * q] = b2.x;
            acc[2 * q + 1] = b2.y;
        }

        // input contribution
        {
            const float* ip = inb + lane;
            const float* Wrow = Wa + w * VPW;
#pragma unroll 2
            for (int k = 0; k < KA; k++) {
                unsigned int xi = __float_as_uint(ip[k * 33]);
                unsigned long long x2;
                asm("mov.b64 %0, {%1,%2};" : "=l"(x2) : "r"(xi), "r"(xi));
                const ulonglong2* Wk =
                    reinterpret_cast<const ulonglong2*>(Wrow + k * ROWP);
#pragma unroll
                for (int q = 0; q < 9; q++) {
                    ulonglong2 ww = Wk[q];
                    FMA2(acc[2 * q], ww.x, x2);
                    FMA2(acc[2 * q + 1], ww.y, x2);
                }
            }
        }
        // recurrent contribution
        {
            const float* hp = hb + lane;
            const float* Wrow = Wb + w * VPW;
#pragma unroll 2
            for (int k = 0; k < HH; k++) {
                unsigned int xi = __float_as_uint(hp[k * 33]);
                unsigned long long x2;
                asm("mov.b64 %0, {%1,%2};" : "=l"(x2) : "r"(xi), "r"(xi));
                const ulonglong2* Wk =
                    reinterpret_cast<const ulonglong2*>(Wrow + k * ROWP);
#pragma unroll
                for (int q = 0; q < 9; q++) {
                    ulonglong2 ww = Wk[q];
                    FMA2(acc[2 * q], ww.x, x2);
                    FMA2(acc[2 * q + 1], ww.y, x2);
                }
            }
        }

        // ---- spill gates (skip the one garbage col i==35)
#pragma unroll
        for (int p = 0; p < 18; p++) {
            float2 v = *reinterpret_cast<float2*>(&acc[p]);
            int i0 = 2 * p;
            gb[(w * CPW + i0) * 33 + lane] = v.x;
            if (i0 + 1 < CPW) gb[(w * CPW + i0 + 1) * 33 + lane] = v.y;
        }
        __syncthreads();

        // ---- elementwise LSTM cell update
#pragma unroll
        for (int ii = 0; ii < (BC * HH + NTHR - 1) / NTHR; ii++) {
            int idx = tid + ii * NTHR;
            if (idx < BC * HH) {
                int n = idx >> 5, r = idx & 31;
                float gi = gb[n * 33 + r];
                float gf = gb[(n + HH) * 33 + r];
                float gg = gb[(n + 2 * HH) * 33 + r];
                float go = gb[(n + 3 * HH) * 33 + r];
                float iv = sigmoidf_(gi);
                float fv = sigmoidf_(gf);
                float gv = tanhf_(gg);
                float ov = sigmoidf_(go);
                float c = fv * cb[n * 33 + r] + iv * gv;
                cb[n * 33 + r] = c;
                float h = ov * tanhf_(c);
                hb[n * 33 + r] = h;
                if (WRITE_SEQ)
                    seq_out[((size_t)t * HH + n) * BB + row0 + r] = h;
            }
        }
        __syncthreads();
    }

    if (FINAL_OUT) {
        for (int idx = tid; idx < BC * HH; idx += NTHR) {
            int n = idx >> 5, r = idx & 31;
            fin_out[n * BB + row0 + r] = hb[n * 33 + r];
        }
    }
}

// head: out = sigmoid(relu(h1 @ W1.T + b1) @ W2.T + b2)
__global__ void __launch_bounds__(NTHR)
head_kernel(const float* __restrict__ h1,  // [H][B]
            const float* __restrict__ W1, const float* __restrict__ b1,
            const float* __restrict__ W2, const float* __restrict__ b2,
            float* __restrict__ out)
{
    __shared__ float sW1[50 * HH];
    __shared__ float sb1[50];
    __shared__ float sW2[50];
    __shared__ float sb2;
    for (int i = threadIdx.x; i < 50 * HH; i += NTHR) sW1[i] = W1[i];
    if (threadIdx.x < 50) {
        sb1[threadIdx.x] = b1[threadIdx.x];
        sW2[threadIdx.x] = W2[threadIdx.x];
    }
    if (threadIdx.x == 0) sb2 = b2[0];
    __syncthreads();

    int row = blockIdx.x * NTHR + threadIdx.x;
    float h[HH];
#pragma unroll
    for (int n = 0; n < HH; n++) h[n] = h1[n * BB + row];

    float o = sb2;
    for (int s = 0; s < 50; s++) {
        float a = sb1[s];
#pragma unroll
        for (int n = 0; n < HH; n++) a += h[n] * sW1[s * HH + n];
        a = fmaxf(a, 0.f);
        o += a * sW2[s];
    }
    out[row] = __fdividef(1.f, 1.f + __expf(-o));
}

extern "C" void kernel_launch(void* const* d_in, const int* in_sizes, int n_in,
                              void* d_out, int out_size)
{
    // robust to whether scalar batch_dim is materialized as input[1]
    int o = (n_in >= 14 && in_sizes[1] == 1) ? 2 : 1;
    const float* data_in = (const float*)d_in[0];
    const float* W_ih0 = (const float*)d_in[o + 0];
    const float* W_hh0 = (const float*)d_in[o + 1];
    const float* b_ih0 = (const float*)d_in[o + 2];
    const float* b_hh0 = (const float*)d_in[o + 3];
    const float* W_ih1 = (const float*)d_in[o + 4];
    const float* W_hh1 = (const float*)d_in[o + 5];
    const float* b_ih1 = (const float*)d_in[o + 6];
    const float* b_hh1 = (const float*)d_in[o + 7];
    const float* W1    = (const float*)d_in[o + 8];
    const float* b1    = (const float*)d_in[o + 9];
    const float* W2    = (const float*)d_in[o + 10];
    const float* b2    = (const float*)d_in[o + 11];

    float *h0p = nullptr, *h1p = nullptr;
    cudaGetSymbolAddress((void**)&h0p, g_h0);
    cudaGetSymbolAddress((void**)&h1p, g_h1);

    const int sm0 = ((DD + HH) * ROWP + ROWP +
                     DD * 33 + HH * 33 * 2 + GG * 33) * 4;   // ~219 KB
    const int sm1 = ((HH + HH) * ROWP + ROWP +
                     HH * 33 + HH * 33 * 2 + GG * 33) * 4;   // ~227 KB

    cudaFuncSetAttribute((const void*)lstm_layer<DD, false, true, false>,
                         cudaFuncAttributeMaxDynamicSharedMemorySize, sm0);
    cudaFuncSetAttribute((const void*)lstm_layer<HH, true, false, true>,
                         cudaFuncAttributeMaxDynamicSharedMemorySize, sm1);

    lstm_layer<DD, false, true, false><<<NBLK, NTHR, sm0>>>(
        data_in, W_ih0, W_hh0, b_ih0, b_hh0, h0p, nullptr);
    lstm_layer<HH, true, false, true><<<NBLK, NTHR, sm1>>>(
        h0p, W_ih1, W_hh1, b_ih1, b_hh1, nullptr, h1p);
    head_kernel<<<BB / NTHR, NTHR>>>(h1p, W1, b1, W2, b2, (float*)d_out);
}

// round 2
// speedup vs baseline: 1.0171x; 1.0171x over previous
#include <cuda_runtime.h>
#include <cstdint>
#include <cstddef>

// ---------------------------------------------------------------------------
// 2-layer LSTM (T=512, B=4096, D=64, H=70) + MLP head.
// R2: MUFU-free activations (FMA-only exp2 + Newton reciprocal),
//     interleaved gate layout (c-state in registers, no gate spill),
//     pre-duplicated f32x2 operands in SMEM.
// ---------------------------------------------------------------------------

#define TT   512
#define BB   4096
#define DD   64
#define HH   70
#define HP   72           // padded hidden (72*4 = 288 gate cols)
#define GP   288          // padded gate width = 8 warps * 36
#define BC   32           // batch rows per block
#define NBLK (BB / BC)    // 128 blocks
#define NTHR 256

// scratch: h0 sequence [T][H][B], final h1 [H][B]
__device__ float g_h0[(size_t)TT * HH * BB];
__device__ float g_h1[HH * BB];

#define FMA2(d, a, b) \
    asm("fma.rn.f32x2 %0, %1, %2, %0;" : "+l"(d) : "l"(a), "l"(b))

__device__ __forceinline__ unsigned long long dup2(float v) {
    unsigned long long r;
    unsigned int u = __float_as_uint(v);
    asm("mov.b64 %0, {%1,%2};" : "=l"(r) : "r"(u), "r"(u));
    return r;
}

// 2^y, FMA/ALU only (no MUFU, no F2I). |err| ~1e-7 rel.
__device__ __forceinline__ float fexp2(float y) {
    y = fminf(fmaxf(y, -28.0f), 28.0f);
    float t = __fadd_rn(y, 12582912.0f);          // round-to-nearest trick
    int   n = __float_as_int(t) - 0x4B400000;
    float f = __fsub_rn(y, __fsub_rn(t, 12582912.0f));
    float p =            1.54035304e-4f;
    p = __fmaf_rn(p, f,  1.33335581e-3f);
    p = __fmaf_rn(p, f,  9.61812911e-3f);
    p = __fmaf_rn(p, f,  5.55041087e-2f);
    p = __fmaf_rn(p, f,  2.40226507e-1f);
    p = __fmaf_rn(p, f,  6.93147181e-1f);
    p = __fmaf_rn(p, f,  1.0f);
    return __int_as_float(__float_as_int(p) + (n << 23));
}

// 1/a for a in [~1e-9, ~1e9], FMA-only Newton (3 iters, err ~1e-10).
__device__ __forceinline__ float frcp(float a) {
    float x = __int_as_float(0x7EF311C3 - __float_as_int(a));
    x = x * __fmaf_rn(-a, x, 2.0f);
    x = x * __fmaf_rn(-a, x, 2.0f);
    x = x * __fmaf_rn(-a, x, 2.0f);
    return x;
}

__device__ __forceinline__ float fsigmoid(float x) {
    return frcp(1.0f + fexp2(x * -1.44269504f));
}
__device__ __forceinline__ float ftanh(float x) {
    return 1.0f - 2.0f * frcp(1.0f + fexp2(x * 2.88539008f));
}

template <int KA, bool IN_TBK, bool WRITE_SEQ, bool FINAL_OUT>
__global__ void __launch_bounds__(NTHR, 1)
lstm_layer(const float* __restrict__ in_seq,
           const float* __restrict__ Wih, const float* __restrict__ Whh,
           const float* __restrict__ bih, const float* __restrict__ bhh,
           float* __restrict__ seq_out, float* __restrict__ fin_out)
{
    extern __shared__ float sm[];
    float* Wa   = sm;                          // [KA][GP], col = 4n+g
    float* Wb   = Wa + KA * GP;                // [HH][GP]
    float* bias = Wb + HH * GP;                // [GP]
    unsigned long long* inb2 =
        reinterpret_cast<unsigned long long*>(bias + GP);   // [KA][33]
    unsigned long long* hb2 = inb2 + KA * 33;               // [HH][33]

    const int tid  = threadIdx.x;
    const int lane = tid & 31;
    const int w    = tid >> 5;
    const int row0 = blockIdx.x * BC;

    // zero weights+bias (covers pad cols) and h buffer
    for (int i = tid; i < (KA + HH) * GP + GP; i += NTHR) sm[i] = 0.f;
    {
        float* hf = reinterpret_cast<float*>(hb2);
        for (int i = tid; i < HH * 33 * 2; i += NTHR) hf[i] = 0.f;
    }
    __syncthreads();

    // transpose weights into [k][4n+g] layout (gate-interleaved)
    for (int idx = tid; idx < 4 * HH * KA; idx += NTHR) {
        int j = idx / KA, k = idx - j * KA;
        int g = j / HH, n = j - g * HH;
        Wa[k * GP + 4 * n + g] = Wih[idx];
    }
    for (int idx = tid; idx < 4 * HH * HH; idx += NTHR) {
        int j = idx / HH, k = idx - j * HH;
        int g = j / HH, n = j - g * HH;
        Wb[k * GP + 4 * n + g] = Whh[idx];
    }
    for (int j = tid; j < 4 * HH; j += NTHR) {
        int g = j / HH, n = j - g * HH;
        bias[4 * n + g] = bih[j] + bhh[j];
    }
    __syncthreads();

    const ulonglong2* bias2 =
        reinterpret_cast<const ulonglong2*>(bias + w * 36);

    float creg[9];
#pragma unroll
    for (int u = 0; u < 9; u++) creg[u] = 0.f;

    for (int t = 0; t < TT; t++) {
        // ---- stage input tile (duplicated pairs)
        if (!IN_TBK) {
            // in_seq [T][B][KA], KA=64
#pragma unroll
            for (int ii = 0; ii < (BC * KA) / NTHR; ii++) {
                int idx = tid + ii * NTHR;
                int r = idx >> 6, k = idx & 63;
                inb2[k * 33 + r] =
                    dup2(in_seq[((size_t)t * BB + row0 + r) * KA + k]);
            }
        } else {
            // in_seq [T][KA][B], KA=70
#pragma unroll
            for (int ii = 0; ii < (BC * KA + NTHR - 1) / NTHR; ii++) {
                int idx = tid + ii * NTHR;
                if (idx < BC * KA) {
                    int k = idx >> 5, r = idx & 31;
                    inb2[k * 33 + r] =
                        dup2(in_seq[((size_t)t * KA + k) * BB + row0 + r]);
                }
            }
        }
        __syncthreads();

        // ---- gates GEMM: warp w -> units [9w, 9w+9), 32 batch rows
        unsigned long long acc[18];
#pragma unroll
        for (int q = 0; q < 9; q++) {
            ulonglong2 b2 = bias2[q];
            acc[2 * q] = b2.x;
            acc[2 * q + 1] = b2.y;
        }
        {
            const unsigned long long* xp = inb2 + lane;
            const float* Wrow = Wa + w * 36;
#pragma unroll 2
            for (int k = 0; k < KA; k++) {
                unsigned long long x2 = xp[k * 33];
                const ulonglong2* Wk =
                    reinterpret_cast<const ulonglong2*>(Wrow + k * GP);
#pragma unroll
                for (int q = 0; q < 9; q++) {
                    ulonglong2 ww = Wk[q];
                    FMA2(acc[2 * q], ww.x, x2);
                    FMA2(acc[2 * q + 1], ww.y, x2);
                }
            }
        }
        {
            const unsigned long long* hp = hb2 + lane;
            const float* Wrow = Wb + w * 36;
#pragma unroll 2
            for (int k = 0; k < HH; k++) {
                unsigned long long x2 = hp[k * 33];
                const ulonglong2* Wk =
                    reinterpret_cast<const ulonglong2*>(Wrow + k * GP);
#pragma unroll
                for (int q = 0; q < 9; q++) {
                    ulonglong2 ww = Wk[q];
                    FMA2(acc[2 * q], ww.x, x2);
                    FMA2(acc[2 * q + 1], ww.y, x2);
                }
            }
        }
        __syncthreads();   // all GEMM reads of hb2 done before overwrite

        // ---- in-register cell update; lane owns batch row `lane`
#pragma unroll
        for (int u = 0; u < 9; u++) {
            int n = 9 * w + u;
            float2 if_ = *reinterpret_cast<float2*>(&acc[2 * u]);
            float2 go_ = *reinterpret_cast<float2*>(&acc[2 * u + 1]);
            float iv = fsigmoid(if_.x);
            float fv = fsigmoid(if_.y);
            float gv = ftanh(go_.x);
            float ov = fsigmoid(go_.y);
            float c = __fmaf_rn(fv, creg[u], iv * gv);
            creg[u] = c;
            float h = ov * ftanh(c);
            if (n < HH) {
                hb2[n * 33 + lane] = dup2(h);
                if (WRITE_SEQ)
                    seq_out[((size_t)t * HH + n) * BB + row0 + lane] = h;
                if (FINAL_OUT && t == TT - 1)
                    fin_out[n * BB + row0 + lane] = h;
            }
        }
        __syncthreads();   // hb2 / inb2 ready for next step
    }
}

// head: out = sigmoid(relu(h1 @ W1.T + b1) @ W2.T + b2)
__global__ void __launch_bounds__(NTHR)
head_kernel(const float* __restrict__ h1,  // [H][B]
            const float* __restrict__ W1, const float* __restrict__ b1,
            const float* __restrict__ W2, const float* __restrict__ b2,
            float* __restrict__ out)
{
    __shared__ float sW1[50 * HH];
    __shared__ float sb1[50];
    __shared__ float sW2[50];
    __shared__ float sb2;
    for (int i = threadIdx.x; i < 50 * HH; i += NTHR) sW1[i] = W1[i];
    if (threadIdx.x < 50) {
        sb1[threadIdx.x] = b1[threadIdx.x];
        sW2[threadIdx.x] = W2[threadIdx.x];
    }
    if (threadIdx.x == 0) sb2 = b2[0];
    __syncthreads();

    int row = blockIdx.x * NTHR + threadIdx.x;
    float h[HH];
#pragma unroll
    for (int n = 0; n < HH; n++) h[n] = h1[n * BB + row];

    float o = sb2;
    for (int s = 0; s < 50; s++) {
        float a = sb1[s];
#pragma unroll
        for (int n = 0; n < HH; n++) a += h[n] * sW1[s * HH + n];
        a = fmaxf(a, 0.f);
        o += a * sW2[s];
    }
    out[row] = fsigmoid(o);
}

extern "C" void kernel_launch(void* const* d_in, const int* in_sizes, int n_in,
                              void* d_out, int out_size)
{
    int o = (n_in >= 14 && in_sizes[1] == 1) ? 2 : 1;
    const float* data_in = (const float*)d_in[0];
    const float* W_ih0 = (const float*)d_in[o + 0];
    const float* W_hh0 = (const float*)d_in[o + 1];
    const float* b_ih0 = (const float*)d_in[o + 2];
    const float* b_hh0 = (const float*)d_in[o + 3];
    const float* W_ih1 = (const float*)d_in[o + 4];
    const float* W_hh1 = (const float*)d_in[o + 5];
    const float* b_ih1 = (const float*)d_in[o + 6];
    const float* b_hh1 = (const float*)d_in[o + 7];
    const float* W1    = (const float*)d_in[o + 8];
    const float* b1    = (const float*)d_in[o + 9];
    const float* W2    = (const float*)d_in[o + 10];
    const float* b2    = (const float*)d_in[o + 11];

    float *h0p = nullptr, *h1p = nullptr;
    cudaGetSymbolAddress((void**)&h0p, g_h0);
    cudaGetSymbolAddress((void**)&h1p, g_h1);

    const int sm0 = ((DD + HH) * GP + GP) * 4 + (DD * 33 + HH * 33) * 8;
    const int sm1 = ((HH + HH) * GP + GP) * 4 + (HH * 33 + HH * 33) * 8;

    cudaFuncSetAttribute((const void*)lstm_layer<DD, false, true, false>,
                         cudaFuncAttributeMaxDynamicSharedMemorySize, sm0);
    cudaFuncSetAttribute((const void*)lstm_layer<HH, true, false, true>,
                         cudaFuncAttributeMaxDynamicSharedMemorySize, sm1);

    lstm_layer<DD, false, true, false><<<NBLK, NTHR, sm0>>>(
        data_in, W_ih0, W_hh0, b_ih0, b_hh0, h0p, nullptr);
    lstm_layer<HH, true, false, true><<<NBLK, NTHR, sm1>>>(
        h0p, W_ih1, W_hh1, b_ih1, b_hh1, nullptr, h1p);
    head_kernel<<<BB / NTHR, NTHR>>>(h1p, W1, b1, W2, b2, (float*)d_out);
}

// round 3
// speedup vs baseline: 1.0182x; 1.0011x over previous
#include <cuda_runtime.h>
#include <cstdint>
#include <cstddef>

// ---------------------------------------------------------------------------
// 2-layer LSTM (T=512, B=4096, D=64, H=70) + MLP head.
// R2: MUFU-free activations (FMA-only exp2 + Newton reciprocal),
//     interleaved gate layout (c-state in registers, no gate spill),
//     pre-duplicated f32x2 operands in SMEM.
// ---------------------------------------------------------------------------

#define TT   512
#define BB   4096
#define DD   64
#define HH   70
#define HP   72           // padded hidden (72*4 = 288 gate cols)
#define GP   288          // padded gate width = 8 warps * 36
#define BC   32           // batch rows per block
#define NBLK (BB / BC)    // 128 blocks
#define NTHR 256

// scratch: h0 sequence [T][H][B], final h1 [H][B]
__device__ float g_h0[(size_t)TT * HH * BB];
__device__ float g_h1[HH * BB];

#define FMA2(d, a, b) \
    asm("fma.rn.f32x2 %0, %1, %2, %0;" : "+l"(d) : "l"(a), "l"(b))

__device__ __forceinline__ unsigned long long dup2(float v) {
    unsigned long long r;
    unsigned int u = __float_as_uint(v);
    asm("mov.b64 %0, {%1,%2};" : "=l"(r) : "r"(u), "r"(u));
    return r;
}

// 2^y, FMA/ALU only (no MUFU, no F2I). |err| ~1e-7 rel.
__device__ __forceinline__ float fexp2(float y) {
    y = fminf(fmaxf(y, -28.0f), 28.0f);
    float t = __fadd_rn(y, 12582912.0f);          // round-to-nearest trick
    int   n = __float_as_int(t) - 0x4B400000;
    float f = __fsub_rn(y, __fsub_rn(t, 12582912.0f));
    float p =            1.54035304e-4f;
    p = __fmaf_rn(p, f,  1.33335581e-3f);
    p = __fmaf_rn(p, f,  9.61812911e-3f);
    p = __fmaf_rn(p, f,  5.55041087e-2f);
    p = __fmaf_rn(p, f,  2.40226507e-1f);
    p = __fmaf_rn(p, f,  6.93147181e-1f);
    p = __fmaf_rn(p, f,  1.0f);
    return __int_as_float(__float_as_int(p) + (n << 23));
}

// 1/a for a in [~1e-9, ~1e9], FMA-only Newton (3 iters, err ~1e-10).
__device__ __forceinline__ float frcp(float a) {
    float x = __int_as_float(0x7EF311C3 - __float_as_int(a));
    x = x * __fmaf_rn(-a, x, 2.0f);
    x = x * __fmaf_rn(-a, x, 2.0f);
    x = x * __fmaf_rn(-a, x, 2.0f);
    return x;
}

__device__ __forceinline__ float fsigmoid(float x) {
    return frcp(1.0f + fexp2(x * -1.44269504f));
}
__device__ __forceinline__ float ftanh(float x) {
    return 1.0f - 2.0f * frcp(1.0f + fexp2(x * 2.88539008f));
}

template <int KA, bool IN_TBK, bool WRITE_SEQ, bool FINAL_OUT>
__global__ void __launch_bounds__(NTHR, 1)
lstm_layer(const float* __restrict__ in_seq,
           const float* __restrict__ Wih, const float* __restrict__ Whh,
           const float* __restrict__ bih, const float* __restrict__ bhh,
           float* __restrict__ seq_out, float* __restrict__ fin_out)
{
    extern __shared__ float sm[];
    float* Wa   = sm;                          // [KA][GP], col = 4n+g
    float* Wb   = Wa + KA * GP;                // [HH][GP]
    float* bias = Wb + HH * GP;                // [GP]
    unsigned long long* inb2 =
        reinterpret_cast<unsigned long long*>(bias + GP);   // [KA][33]
    unsigned long long* hb2 = inb2 + KA * 33;               // [HH][33]

    const int tid  = threadIdx.x;
    const int lane = tid & 31;
    const int w    = tid >> 5;
    const int row0 = blockIdx.x * BC;

    // zero weights+bias (covers pad cols) and h buffer
    for (int i = tid; i < (KA + HH) * GP + GP; i += NTHR) sm[i] = 0.f;
    {
        float* hf = reinterpret_cast<float*>(hb2);
        for (int i = tid; i < HH * 33 * 2; i += NTHR) hf[i] = 0.f;
    }
    __syncthreads();

    // transpose weights into [k][4n+g] layout (gate-interleaved)
    for (int idx = tid; idx < 4 * HH * KA; idx += NTHR) {
        int j = idx / KA, k = idx - j * KA;
        int g = j / HH, n = j - g * HH;
        Wa[k * GP + 4 * n + g] = Wih[idx];
    }
    for (int idx = tid; idx < 4 * HH * HH; idx += NTHR) {
        int j = idx / HH, k = idx - j * HH;
        int g = j / HH, n = j - g * HH;
        Wb[k * GP + 4 * n + g] = Whh[idx];
    }
    for (int j = tid; j < 4 * HH; j += NTHR) {
        int g = j / HH, n = j - g * HH;
        bias[4 * n + g] = bih[j] + bhh[j];
    }
    __syncthreads();

    const ulonglong2* bias2 =
        reinterpret_cast<const ulonglong2*>(bias + w * 36);

    float creg[9];
#pragma unroll
    for (int u = 0; u < 9; u++) creg[u] = 0.f;

    for (int t = 0; t < TT; t++) {
        // ---- stage input tile (duplicated pairs)
        if (!IN_TBK) {
            // in_seq [T][B][KA], KA=64
#pragma unroll
            for (int ii = 0; ii < (BC * KA) / NTHR; ii++) {
                int idx = tid + ii * NTHR;
                int r = idx >> 6, k = idx & 63;
                inb2[k * 33 + r] =
                    dup2(in_seq[((size_t)t * BB + row0 + r) * KA + k]);
            }
        } else {
            // in_seq [T][KA][B], KA=70
#pragma unroll
            for (int ii = 0; ii < (BC * KA + NTHR - 1) / NTHR; ii++) {
                int idx = tid + ii * NTHR;
                if (idx < BC * KA) {
                    int k = idx >> 5, r = idx & 31;
                    inb2[k * 33 + r] =
                        dup2(in_seq[((size_t)t * KA + k) * BB + row0 + r]);
                }
            }
        }
        __syncthreads();

        // ---- gates GEMM: warp w -> units [9w, 9w+9), 32 batch rows
        unsigned long long acc[18];
#pragma unroll
        for (int q = 0; q < 9; q++) {
            ulonglong2 b2 = bias2[q];
            acc[2 * q] = b2.x;
            acc[2 * q + 1] = b2.y;
        }
        {
            const unsigned long long* xp = inb2 + lane;
            const float* Wrow = Wa + w * 36;
#pragma unroll 2
            for (int k = 0; k < KA; k++) {
                unsigned long long x2 = xp[k * 33];
                const ulonglong2* Wk =
                    reinterpret_cast<const ulonglong2*>(Wrow + k * GP);
#pragma unroll
                for (int q = 0; q < 9; q++) {
                    ulonglong2 ww = Wk[q];
                    FMA2(acc[2 * q], ww.x, x2);
                    FMA2(acc[2 * q + 1], ww.y, x2);
                }
            }
        }
        {
            const unsigned long long* hp = hb2 + lane;
            const float* Wrow = Wb + w * 36;
#pragma unroll 2
            for (int k = 0; k < HH; k++) {
                unsigned long long x2 = hp[k * 33];
                const ulonglong2* Wk =
                    reinterpret_cast<const ulonglong2*>(Wrow + k * GP);
#pragma unroll
                for (int q = 0; q < 9; q++) {
                    ulonglong2 ww = Wk[q];
                    FMA2(acc[2 * q], ww.x, x2);
                    FMA2(acc[2 * q + 1], ww.y, x2);
                }
            }
        }
        __syncthreads();   // all GEMM reads of hb2 done before overwrite

        // ---- in-register cell update; lane owns batch row `lane`
#pragma unroll
        for (int u = 0; u < 9; u++) {
            int n = 9 * w + u;
            float2 if_ = *reinterpret_cast<float2*>(&acc[2 * u]);
            float2 go_ = *reinterpret_cast<float2*>(&acc[2 * u + 1]);
            float iv = fsigmoid(if_.x);
            float fv = fsigmoid(if_.y);
            float gv = ftanh(go_.x);
            float ov = fsigmoid(go_.y);
            float c = __fmaf_rn(fv, creg[u], iv * gv);
            creg[u] = c;
            float h = ov * ftanh(c);
            if (n < HH) {
                hb2[n * 33 + lane] = dup2(h);
                if (WRITE_SEQ)
                    seq_out[((size_t)t * HH + n) * BB + row0 + lane] = h;
                if (FINAL_OUT && t == TT - 1)
                    fin_out[n * BB + row0 + lane] = h;
            }
        }
        __syncthreads();   // hb2 / inb2 ready for next step
    }
}

// head: out = sigmoid(relu(h1 @ W1.T + b1) @ W2.T + b2)
__global__ void __launch_bounds__(NTHR)
head_kernel(const float* __restrict__ h1,  // [H][B]
            const float* __restrict__ W1, const float* __restrict__ b1,
            const float* __restrict__ W2, const float* __restrict__ b2,
            float* __restrict__ out)
{
    __shared__ float sW1[50 * HH];
    __shared__ float sb1[50];
    __shared__ float sW2[50];
    __shared__ float sb2;
    for (int i = threadIdx.x; i < 50 * HH; i += NTHR) sW1[i] = W1[i];
    if (threadIdx.x < 50) {
        sb1[threadIdx.x] = b1[threadIdx.x];
        sW2[threadIdx.x] = W2[threadIdx.x];
    }
    if (threadIdx.x == 0) sb2 = b2[0];
    __syncthreads();

    int row = blockIdx.x * NTHR + threadIdx.x;
    float h[HH];
#pragma unroll
    for (int n = 0; n < HH; n++) h[n] = h1[n * BB + row];

    float o = sb2;
    for (int s = 0; s < 50; s++) {
        float a = sb1[s];
#pragma unroll
        for (int n = 0; n < HH; n++) a += h[n] * sW1[s * HH + n];
        a = fmaxf(a, 0.f);
        o += a * sW2[s];
    }
    out[row] = fsigmoid(o);
}

extern "C" void kernel_launch(void* const* d_in, const int* in_sizes, int n_in,
                              void* d_out, int out_size)
{
    int o = (n_in >= 14 && in_sizes[1] == 1) ? 2 : 1;
    const float* data_in = (const float*)d_in[0];
    const float* W_ih0 = (const float*)d_in[o + 0];
    const float* W_hh0 = (const float*)d_in[o + 1];
    const float* b_ih0 = (const float*)d_in[o + 2];
    const float* b_hh0 = (const float*)d_in[o + 3];
    const float* W_ih1 = (const float*)d_in[o + 4];
    const float* W_hh1 = (const float*)d_in[o + 5];
    const float* b_ih1 = (const float*)d_in[o + 6];
    const float* b_hh1 = (const float*)d_in[o + 7];
    const float* W1    = (const float*)d_in[o + 8];
    const float* b1    = (const float*)d_in[o + 9];
    const float* W2    = (const float*)d_in[o + 10];
    const float* b2    = (const float*)d_in[o + 11];

    float *h0p = nullptr, *h1p = nullptr;
    cudaGetSymbolAddress((void**)&h0p, g_h0);
    cudaGetSymbolAddress((void**)&h1p, g_h1);

    const int sm0 = ((DD + HH) * GP + GP) * 4 + (DD * 33 + HH * 33) * 8;
    const int sm1 = ((HH + HH) * GP + GP) * 4 + (HH * 33 + HH * 33) * 8;

    cudaFuncSetAttribute((const void*)lstm_layer<DD, false, true, false>,
                         cudaFuncAttributeMaxDynamicSharedMemorySize, sm0);
    cudaFuncSetAttribute((const void*)lstm_layer<HH, true, false, true>,
                         cudaFuncAttributeMaxDynamicSharedMemorySize, sm1);

    lstm_layer<DD, false, true, false><<<NBLK, NTHR, sm0>>>(
        data_in, W_ih0, W_hh0, b_ih0, b_hh0, h0p, nullptr);
    lstm_layer<HH, true, false, true><<<NBLK, NTHR, sm1>>>(
        h0p, W_ih1, W_hh1, b_ih1, b_hh1, nullptr, h1p);
    head_kernel<<<BB / NTHR, NTHR>>>(h1p, W1, b1, W2, b2, (float*)d_out);
}